// round 7
// baseline (speedup 1.0000x reference)
#include <cuda_runtime.h>
#include <cuda_bf16.h>
#include <cstdint>

#define USER_NUM 80000
#define ITEM_NUM 40000
#define NTOT     (USER_NUM + ITEM_NUM)   // 120000
#define EMB      64
#define NNZ      1200000
#define N_LAYERS 3

#define TOTAL_F  (NTOT * EMB)            // 7,680,000 floats
#define TOTAL_V4 (TOTAL_F / 4)           // 1,920,000 float4

// Scratch (allocation-free rule: __device__ globals)
__device__ float g_bufA[TOTAL_F];
__device__ float g_bufB[TOTAL_F];
__device__ int4  g_edges[NNZ];           // packed (row, col, val_bits, pad) — 19.2 MB

// ---------------------------------------------------------------------------
// pack: g_edges[i] = {rows[i], cols[i], bits(vals[i]), 0}
// One coalesced 16B store per edge; replaces 3 redundant scalar loads per
// spmm work-item with a single broadcast LDG.128.
// ---------------------------------------------------------------------------
__global__ void pack_kernel(const float* __restrict__ vals,
                            const int*   __restrict__ rows,
                            const int*   __restrict__ cols) {
    int i = blockIdx.x * blockDim.x + threadIdx.x;
    if (i >= NNZ) return;
    int4 m;
    m.x = rows[i];
    m.y = cols[i];
    m.z = __float_as_int(vals[i]);
    m.w = 0;
    g_edges[i] = m;
}

// ---------------------------------------------------------------------------
// init: A = concat(user_emb, item_emb), B = 0
// ---------------------------------------------------------------------------
__global__ void init_kernel(const float4* __restrict__ user4,
                            const float4* __restrict__ item4) {
    int i = blockIdx.x * blockDim.x + threadIdx.x;
    if (i >= TOTAL_V4) return;
    float4* A4 = reinterpret_cast<float4*>(g_bufA);
    float4* B4 = reinterpret_cast<float4*>(g_bufB);
    const int user_v4 = USER_NUM * EMB / 4;   // 1,280,000
    float4 v;
    if (i < user_v4) v = user4[i];
    else             v = item4[i - user_v4];
    A4[i] = v;
    B4[i] = make_float4(0.f, 0.f, 0.f, 0.f);
}

// ---------------------------------------------------------------------------
// COO SpMM scatter: y[rows[e]] += vals[e] * x[cols[e]]
// dir==0 : x = g_bufA, y = g_bufB ;  dir==1 : x = g_bufB, y = g_bufA
// 16 threads per nonzero. Per thread: 1 broadcast LDG.128 (edge meta),
// 1 gather LDG.128, 1 RED.ADD.v4 — 3 LSU instructions total.
// ---------------------------------------------------------------------------
__global__ void spmm_kernel(int dir) {
    long long t = (long long)blockIdx.x * blockDim.x + threadIdx.x;
    if (t >= (long long)NNZ * 16) return;
    int e = (int)(t >> 4);          // nonzero index
    int c = ((int)t & 15) * 4;      // element offset within the 64-wide row

    const float* x = dir ? g_bufB : g_bufA;
    float*       y = dir ? g_bufA : g_bufB;

    int4 m = g_edges[e];            // same address across 16 lanes -> broadcast
    int   r  = m.x;
    int   cl = m.y;
    float v  = __int_as_float(m.z);

    const float4 xv = *reinterpret_cast<const float4*>(x + (size_t)cl * EMB + c);
    float4 p;
    p.x = v * xv.x; p.y = v * xv.y; p.z = v * xv.z; p.w = v * xv.w;

    float* dst = y + (size_t)r * EMB + c;
#if __CUDA_ARCH__ >= 900
    atomicAdd(reinterpret_cast<float4*>(dst), p);
#else
    atomicAdd(dst + 0, p.x);
    atomicAdd(dst + 1, p.y);
    atomicAdd(dst + 2, p.z);
    atomicAdd(dst + 3, p.w);
#endif
}

// ---------------------------------------------------------------------------
// accumulate: out (+)= src * (1/3); optionally zero the buffer that becomes
// the next layer's scatter target.
// which==0 : src = g_bufB, zero g_bufA
// which==1 : src = g_bufA, zero g_bufB
// which==2 : src = g_bufB, zero nothing
// ---------------------------------------------------------------------------
__global__ void accum_kernel(float4* __restrict__ out4, int which, int first) {
    int i = blockIdx.x * blockDim.x + threadIdx.x;
    if (i >= TOTAL_V4) return;
    const float4* src4 = (which == 1) ? reinterpret_cast<const float4*>(g_bufA)
                                      : reinterpret_cast<const float4*>(g_bufB);
    float4* zero4 = nullptr;
    if (which == 0) zero4 = reinterpret_cast<float4*>(g_bufA);
    if (which == 1) zero4 = reinterpret_cast<float4*>(g_bufB);

    const float inv3 = 1.0f / 3.0f;
    float4 y = src4[i];
    float4 o;
    if (first) {
        o.x = y.x * inv3; o.y = y.y * inv3; o.z = y.z * inv3; o.w = y.w * inv3;
    } else {
        float4 a = out4[i];
        o.x = a.x + y.x * inv3; o.y = a.y + y.y * inv3;
        o.z = a.z + y.z * inv3; o.w = a.w + y.w * inv3;
    }
    out4[i] = o;
    if (zero4) zero4[i] = make_float4(0.f, 0.f, 0.f, 0.f);
}

// ---------------------------------------------------------------------------
// launch: nothing but kernel launches — trivially graph-capturable.
// ---------------------------------------------------------------------------
extern "C" void kernel_launch(void* const* d_in, const int* in_sizes, int n_in,
                              void* d_out, int out_size) {
    const float* user_emb = (const float*)d_in[0];
    const float* item_emb = (const float*)d_in[1];
    const float* adj_vals = (const float*)d_in[2];
    const int*   adj_rows = (const int*)d_in[3];
    const int*   adj_cols = (const int*)d_in[4];
    float4* out = (float4*)d_out;

    const int TB = 256;
    const int gridV4 = (TOTAL_V4 + TB - 1) / TB;
    const int gridP  = (NNZ + TB - 1) / TB;
    const long long spmm_threads = (long long)NNZ * 16;
    const int gridS = (int)((spmm_threads + TB - 1) / TB);

    // Pack edge metadata; A = ego, B = 0 (independent kernels)
    pack_kernel<<<gridP, TB>>>(adj_vals, adj_rows, adj_cols);
    init_kernel<<<gridV4, TB>>>((const float4*)user_emb, (const float4*)item_emb);

    // Layer 0: spmm A->B ; out = B/3 ; zero A (next scatter target)
    spmm_kernel<<<gridS, TB>>>(0);
    accum_kernel<<<gridV4, TB>>>(out, 0, 1);

    // Layer 1: spmm B->A ; out += A/3 ; zero B
    spmm_kernel<<<gridS, TB>>>(1);
    accum_kernel<<<gridV4, TB>>>(out, 1, 0);

    // Layer 2: spmm A->B ; out += B/3
    spmm_kernel<<<gridS, TB>>>(0);
    accum_kernel<<<gridV4, TB>>>(out, 2, 0);
}

// round 8
// speedup vs baseline: 1.6843x; 1.6843x over previous
#include <cuda_runtime.h>
#include <cuda_bf16.h>
#include <cstdint>

#define USER_NUM 80000
#define ITEM_NUM 40000
#define NTOT     (USER_NUM + ITEM_NUM)   // 120000
#define EMB      64
#define NNZ      1200000
#define N_LAYERS 3

#define TOTAL_F  (NTOT * EMB)            // 7,680,000 floats
#define TOTAL_V4 (TOTAL_F / 4)           // 1,920,000 float4

#define SCAN_BS  1024
#define NBLK     ((NTOT + SCAN_BS - 1) / SCAN_BS)   // 118

// Scratch (allocation-free rule: __device__ globals)
__device__ float g_bufA[TOTAL_F];
__device__ float g_bufB[TOTAL_F];
__device__ int   g_cnt[NTOT];
__device__ int   g_rowptr[NTOT + 1];
__device__ int   g_cursor[NTOT];
__device__ int   g_blocksums[NBLK];
__device__ int2  g_sorted[NNZ];          // (col, val_bits), grouped by row

// ---------------------------------------------------------------------------
// Stage 1: histogram of row counts
// ---------------------------------------------------------------------------
__global__ void zero_cnt_kernel() {
    int i = blockIdx.x * blockDim.x + threadIdx.x;
    if (i < NTOT) g_cnt[i] = 0;
}

__global__ void hist_kernel(const int* __restrict__ rows) {
    int e = blockIdx.x * blockDim.x + threadIdx.x;
    if (e < NNZ) atomicAdd(&g_cnt[rows[e]], 1);
}

// ---------------------------------------------------------------------------
// Stage 2: exclusive scan of g_cnt -> g_rowptr (two-level)
// ---------------------------------------------------------------------------
__global__ void scan_blocks_kernel() {
    __shared__ int s[SCAN_BS];
    int b = blockIdx.x, t = threadIdx.x;
    int i = b * SCAN_BS + t;
    int v = (i < NTOT) ? g_cnt[i] : 0;
    s[t] = v;
    __syncthreads();
    for (int off = 1; off < SCAN_BS; off <<= 1) {
        int add = (t >= off) ? s[t - off] : 0;
        __syncthreads();
        s[t] += add;
        __syncthreads();
    }
    if (i < NTOT) g_rowptr[i] = s[t] - v;            // exclusive within block
    if (t == SCAN_BS - 1) g_blocksums[b] = s[t];      // block total
}

__global__ void scan_sums_kernel() {                  // 1 block, 128 threads
    __shared__ int s[128];
    int t = threadIdx.x;
    int v = (t < NBLK) ? g_blocksums[t] : 0;
    s[t] = v;
    __syncthreads();
    for (int off = 1; off < 128; off <<= 1) {
        int add = (t >= off) ? s[t - off] : 0;
        __syncthreads();
        s[t] += add;
        __syncthreads();
    }
    if (t < NBLK) g_blocksums[t] = s[t] - v;          // exclusive
}

__global__ void add_offsets_kernel() {
    int i = blockIdx.x * blockDim.x + threadIdx.x;
    if (i < NTOT) {
        int rp = g_rowptr[i] + g_blocksums[i / SCAN_BS];
        g_rowptr[i] = rp;
        g_cursor[i] = rp;
    }
    if (i == 0) g_rowptr[NTOT] = NNZ;
}

// ---------------------------------------------------------------------------
// Stage 3: scatter edges into row-grouped order
// ---------------------------------------------------------------------------
__global__ void scatter_kernel(const float* __restrict__ vals,
                               const int*   __restrict__ rows,
                               const int*   __restrict__ cols) {
    int e = blockIdx.x * blockDim.x + threadIdx.x;
    if (e >= NNZ) return;
    int r = rows[e];
    int pos = atomicAdd(&g_cursor[r], 1);
    int2 m;
    m.x = cols[e];
    m.y = __float_as_int(vals[e]);
    g_sorted[pos] = m;
}

// ---------------------------------------------------------------------------
// init: A = concat(user_emb, item_emb)   (no zeroing needed anywhere)
// ---------------------------------------------------------------------------
__global__ void init_kernel(const float4* __restrict__ user4,
                            const float4* __restrict__ item4) {
    int i = blockIdx.x * blockDim.x + threadIdx.x;
    if (i >= TOTAL_V4) return;
    float4* A4 = reinterpret_cast<float4*>(g_bufA);
    const int user_v4 = USER_NUM * EMB / 4;   // 1,280,000
    A4[i] = (i < user_v4) ? user4[i] : item4[i - user_v4];
}

// ---------------------------------------------------------------------------
// Fused CSR SpMM + layer accumulate.
// 16 threads per row; each thread owns one float4 column slice.
//   y[r] = sum_{e in row r} val[e] * x[col[e]]      (register accumulation)
//   out[r] (+)= y[r] / 3
// dir==0: x=A, y=B ; dir==1: x=B, y=A.  last==1 skips the y store.
// No atomics, no destination zeroing.
// ---------------------------------------------------------------------------
__global__ void spmm_fused_kernel(float4* __restrict__ out4,
                                  int dir, int first, int last) {
    int t = blockIdx.x * blockDim.x + threadIdx.x;
    if (t >= NTOT * 16) return;
    int r    = t >> 4;
    int c    = (t & 15) * 4;

    const float* x = dir ? g_bufB : g_bufA;
    float*       y = dir ? g_bufA : g_bufB;

    int beg = g_rowptr[r];
    int end = g_rowptr[r + 1];

    float4 acc = make_float4(0.f, 0.f, 0.f, 0.f);
    for (int i = beg; i < end; ++i) {
        int2  m = g_sorted[i];                        // broadcast across 16 lanes
        float v = __int_as_float(m.y);
        const float4 xv = *reinterpret_cast<const float4*>(
            x + (size_t)m.x * EMB + c);
        acc.x += v * xv.x; acc.y += v * xv.y;
        acc.z += v * xv.z; acc.w += v * xv.w;
    }

    size_t o = (size_t)t;                             // r*16 + lane
    if (!last) reinterpret_cast<float4*>(y)[o] = acc;

    const float inv3 = 1.0f / 3.0f;
    float4 res;
    if (first) {
        res.x = acc.x * inv3; res.y = acc.y * inv3;
        res.z = acc.z * inv3; res.w = acc.w * inv3;
    } else {
        float4 a = out4[o];
        res.x = a.x + acc.x * inv3; res.y = a.y + acc.y * inv3;
        res.z = a.z + acc.z * inv3; res.w = a.w + acc.w * inv3;
    }
    out4[o] = res;
}

// ---------------------------------------------------------------------------
// launch: nothing but kernel launches — trivially graph-capturable.
// ---------------------------------------------------------------------------
extern "C" void kernel_launch(void* const* d_in, const int* in_sizes, int n_in,
                              void* d_out, int out_size) {
    const float* user_emb = (const float*)d_in[0];
    const float* item_emb = (const float*)d_in[1];
    const float* adj_vals = (const float*)d_in[2];
    const int*   adj_rows = (const int*)d_in[3];
    const int*   adj_cols = (const int*)d_in[4];
    float4* out = (float4*)d_out;

    const int TB = 256;
    const int gridN  = (NTOT + TB - 1) / TB;          // 469
    const int gridE  = (NNZ + TB - 1) / TB;           // 4688
    const int gridV4 = (TOTAL_V4 + TB - 1) / TB;      // 7500
    const int gridS  = (NTOT * 16 + TB - 1) / TB;     // 7500

    // CSR build (counting sort by row)
    zero_cnt_kernel<<<gridN, TB>>>();
    hist_kernel<<<gridE, TB>>>(adj_rows);
    scan_blocks_kernel<<<NBLK, SCAN_BS>>>();
    scan_sums_kernel<<<1, 128>>>();
    add_offsets_kernel<<<gridN, TB>>>();
    scatter_kernel<<<gridE, TB>>>(adj_vals, adj_rows, adj_cols);

    // ego embeddings
    init_kernel<<<gridV4, TB>>>((const float4*)user_emb, (const float4*)item_emb);

    // 3 fused layers: spmm + out accumulation, no atomics
    spmm_fused_kernel<<<gridS, TB>>>(out, 0, 1, 0);   // A->B, out  = B/3
    spmm_fused_kernel<<<gridS, TB>>>(out, 1, 0, 0);   // B->A, out += A/3
    spmm_fused_kernel<<<gridS, TB>>>(out, 0, 0, 1);   // A->B, out += B/3 (skip y)
}